// round 1
// baseline (speedup 1.0000x reference)
#include <cuda_runtime.h>
#include <math.h>
#include <stdint.h>

#define SEQ 6912
#define DIM 1536
#define NH  12
#define HD  128
#define Fg  12
#define Hg  24
#define Wg  24
#define FK  288           // f*k = 12*24
#define EPS_NORM 1e-6f
#define CAPF (1.0f/1.000001f)   // min(1/(1+eps), 1e4) with cR == 1

// ---------------- scratch (device globals; no runtime allocation) ----------
__device__ float g_q[SEQ * DIM];
__device__ float g_k[SEQ * DIM];
__device__ float g_v[SEQ * DIM];
__device__ float g_attn[SEQ * DIM];
// layout: [h][a][j][fk][d]  (a in 0..11, j in 0..23, fk = f*24 + k)
__device__ float g_aL[(size_t)NH * Fg * Wg * FK * HD];
__device__ float g_Y [(size_t)NH * Fg * Wg * FK * HD];
__device__ float g_cL[(size_t)NH * Fg * Wg * FK];

// ---------------- GEMM: out[m,o] = sum_k A[m,k] * W[o,k] + bias[o] ----------
// A: [M,K] row-major, W: [O,K] row-major (i.e. computes A @ W^T + b)
// BM=BN=128, BK=8, 256 threads, 8x8 micro-tile.
__global__ __launch_bounds__(256) void gemm_bias(
    const float* __restrict__ A, const float* __restrict__ W,
    const float* __restrict__ bias, float* __restrict__ out,
    int M, int K, int O)
{
    __shared__ float As[8 * 132];
    __shared__ float Ws[8 * 132];

    const int tid = threadIdx.x;
    const int tx = tid & 15;       // 0..15
    const int ty = tid >> 4;       // 0..15
    const int m0 = blockIdx.y * 128;
    const int o0 = blockIdx.x * 128;

    float acc[8][8];
#pragma unroll
    for (int r = 0; r < 8; r++)
#pragma unroll
        for (int c = 0; c < 8; c++) acc[r][c] = 0.f;

    const int lrow = tid >> 1;          // 0..127
    const int lk   = (tid & 1) * 4;     // 0 or 4
    const float* Aptr = A + (size_t)(m0 + lrow) * K + lk;
    const float* Wptr = W + (size_t)(o0 + lrow) * K + lk;

    for (int k0 = 0; k0 < K; k0 += 8) {
        float4 a4 = *reinterpret_cast<const float4*>(Aptr + k0);
        float4 w4 = *reinterpret_cast<const float4*>(Wptr + k0);
        As[(lk + 0) * 132 + lrow] = a4.x;
        As[(lk + 1) * 132 + lrow] = a4.y;
        As[(lk + 2) * 132 + lrow] = a4.z;
        As[(lk + 3) * 132 + lrow] = a4.w;
        Ws[(lk + 0) * 132 + lrow] = w4.x;
        Ws[(lk + 1) * 132 + lrow] = w4.y;
        Ws[(lk + 2) * 132 + lrow] = w4.z;
        Ws[(lk + 3) * 132 + lrow] = w4.w;
        __syncthreads();

#pragma unroll
        for (int kk = 0; kk < 8; kk++) {
            float4 a0 = *reinterpret_cast<const float4*>(&As[kk * 132 + ty * 8]);
            float4 a1 = *reinterpret_cast<const float4*>(&As[kk * 132 + ty * 8 + 4]);
            float4 w0 = *reinterpret_cast<const float4*>(&Ws[kk * 132 + tx * 8]);
            float4 w1 = *reinterpret_cast<const float4*>(&Ws[kk * 132 + tx * 8 + 4]);
            float ar[8] = {a0.x, a0.y, a0.z, a0.w, a1.x, a1.y, a1.z, a1.w};
            float wr[8] = {w0.x, w0.y, w0.z, w0.w, w1.x, w1.y, w1.z, w1.w};
#pragma unroll
            for (int r = 0; r < 8; r++)
#pragma unroll
                for (int c = 0; c < 8; c++)
                    acc[r][c] += ar[r] * wr[c];
        }
        __syncthreads();
    }

#pragma unroll
    for (int r = 0; r < 8; r++) {
        int m = m0 + ty * 8 + r;
#pragma unroll
        for (int c = 0; c < 8; c++) {
            int o = o0 + tx * 8 + c;
            out[(size_t)m * O + o] = acc[r][c] + bias[o];
        }
    }
}

// ---------------- fused RMSNorm (over DIM) + 3D RoPE + scale, in-place ------
__global__ __launch_bounds__(256) void norm_rope(
    float* __restrict__ data, const float* __restrict__ g,
    const float* __restrict__ freqs, float scale)
{
    const int s = blockIdx.x;
    float* row = data + (size_t)s * DIM;
    const int tid = threadIdx.x;

    float ss = 0.f;
    for (int c = tid; c < DIM; c += 256) { float v = row[c]; ss += v * v; }
#pragma unroll
    for (int off = 16; off; off >>= 1) ss += __shfl_xor_sync(~0u, ss, off);
    __shared__ float red[8];
    __shared__ float s_rms;
    if ((tid & 31) == 0) red[tid >> 5] = ss;
    __syncthreads();
    if (tid == 0) {
        float t = 0.f;
#pragma unroll
        for (int i = 0; i < 8; i++) t += red[i];
        s_rms = rsqrtf(t / (float)DIM + EPS_NORM);
    }
    __syncthreads();
    const float rms = s_rms;

    const int fidx = s / (Hg * Wg);
    const int rem  = s % (Hg * Wg);
    const int hidx = rem / Wg;
    const int widx = rem % Wg;

    for (int p = tid; p < DIM / 2; p += 256) {
        const int n = p >> 6;      // head
        const int m = p & 63;      // pair index within head
        const int pos = (m < 22) ? fidx : (m < 43) ? hidx : widx;
        const float ang = freqs[pos * 64 + m];
        float sn, cs;
        sincosf(ang, &sn, &cs);
        const int c0 = n * HD + 2 * m;
        const float xr = row[c0]     * rms * g[c0];
        const float xi = row[c0 + 1] * rms * g[c0 + 1];
        row[c0]     = (xr * cs - xi * sn) * scale;
        row[c0 + 1] = (xr * sn + xi * cs) * scale;
    }
}

// ---------------- Stage A: right softmax over l, produce aL, Y, cL ----------
// grid (k=24, f=12, h=12); 256 threads = 8 warps; each warp processes rows
// r in [0,288) step 8, row -> (a = r/24, j = r%24).
__global__ __launch_bounds__(256) void stageA()
{
    const int kb = blockIdx.x;   // H index shared by queries and keys
    const int f  = blockIdx.y;
    const int h  = blockIdx.z;

    __shared__ float Ksh[HD * 25];   // [d][l], stride 25
    __shared__ float Vsh[HD * 25];
    __shared__ float qsh[8 * HD];

    const int tid = threadIdx.x, lane = tid & 31, w = tid >> 5;
    const int sk_base = f * (Hg * Wg) + kb * Wg;

    for (int idx = tid; idx < 24 * HD; idx += 256) {
        const int l = idx >> 7, d = idx & 127;
        const size_t gidx = (size_t)(sk_base + l) * DIM + h * HD + d;
        Ksh[d * 25 + l] = g_k[gidx];
        Vsh[d * 25 + l] = g_v[gidx];
    }
    __syncthreads();

    for (int r = w; r < Fg * Wg; r += 8) {
        const int a = r / Wg, j = r % Wg;
        const int sq = a * (Hg * Wg) + kb * Wg + j;

        // stage q row into smem
        const float4 q4 = *reinterpret_cast<const float4*>(
            &g_q[(size_t)sq * DIM + h * HD + lane * 4]);
        *reinterpret_cast<float4*>(&qsh[w * HD + lane * 4]) = q4;
        __syncwarp();

        float z;
        if (lane < 24) {
            float acc = 0.f;
#pragma unroll 8
            for (int d = 0; d < HD; d++)
                acc += qsh[w * HD + d] * Ksh[d * 25 + lane];
            z = acc * CAPF;
        } else {
            z = -INFINITY;
        }
        float zm = z;
#pragma unroll
        for (int off = 16; off; off >>= 1)
            zm = fmaxf(zm, __shfl_xor_sync(~0u, zm, off));
        const float e  = (lane < 24) ? expf(z - zm) : 0.f;
        const float et = (lane < 24) ? e * (z - zm) : 0.f;
        float es = e, ets = et;
#pragma unroll
        for (int off = 16; off; off >>= 1) {
            es  += __shfl_xor_sync(~0u, es, off);
            ets += __shfl_xor_sync(~0u, ets, off);
        }
        const float inv = 1.f / es;
        const float R   = e * inv;
        const float cl  = ets * inv - logf(es);

        float accA[4] = {0.f, 0.f, 0.f, 0.f};
        float accY[4] = {0.f, 0.f, 0.f, 0.f};
#pragma unroll
        for (int l = 0; l < 24; l++) {
            const float rl = __shfl_sync(~0u, R, l);
#pragma unroll
            for (int t = 0; t < 4; t++) {
                const int d = lane + 32 * t;
                accA[t] += rl * Ksh[d * 25 + l];
                accY[t] += rl * Vsh[d * 25 + l];
            }
        }

        const size_t rowbase =
            ((size_t)(h * Fg + a) * Wg + j) * FK + (f * 24 + kb);
        const size_t ob = rowbase * HD;
#pragma unroll
        for (int t = 0; t < 4; t++) {
            g_aL[ob + lane + 32 * t] = accA[t];
            g_Y [ob + lane + 32 * t] = accY[t];
        }
        if (lane == 0) g_cL[rowbase] = cl;
        __syncwarp();
    }
}

// ---------------- Stage B: left block softmax over (f,k), output attn -------
// grid (j=24, a=12, h=12); 256 threads.
__global__ __launch_bounds__(256) void stageB()
{
    const int j = blockIdx.x;
    const int a = blockIdx.y;
    const int h = blockIdx.z;

    __shared__ float Qsh[HD * 25];    // [d][i]
    __shared__ float bLsh[FK * 25];   // [fk][i], stride 25
    __shared__ float alsh[8 * HD];
    __shared__ float red[8 * 24];
    __shared__ float msh[24], invsh[24];

    const int tid = threadIdx.x, lane = tid & 31, w = tid >> 5;

    for (int idx = tid; idx < 24 * HD; idx += 256) {
        const int i = idx >> 7, d = idx & 127;
        Qsh[d * 25 + i] =
            g_q[(size_t)(a * 576 + i * 24 + j) * DIM + h * HD + d];
    }
    __syncthreads();

    const size_t base   = (size_t)(h * Fg + a) * Wg + j;
    const size_t albase = base * FK * HD;
    const size_t clbase = base * FK;

    // phase 1: bL[fk][i] = aL[fk,:] . Q[i,:] - cL[fk]
    for (int fk = w; fk < FK; fk += 8) {
        const float4 a4 = *reinterpret_cast<const float4*>(
            &g_aL[albase + (size_t)fk * HD + lane * 4]);
        *reinterpret_cast<float4*>(&alsh[w * HD + lane * 4]) = a4;
        __syncwarp();
        if (lane < 24) {
            float b = 0.f;
#pragma unroll 8
            for (int d = 0; d < HD; d++)
                b += alsh[w * HD + d] * Qsh[d * 25 + lane];
            bLsh[fk * 25 + lane] = b - g_cL[clbase + fk];
        }
        __syncwarp();
    }
    __syncthreads();

    // phase 2: softmax over fk (288) for each i (24)
    const int gi = tid % 24, gg = tid / 24;
    if (tid < 192) {
        float pm = -INFINITY;
        for (int q = 0; q < 36; q++)
            pm = fmaxf(pm, bLsh[(gg * 36 + q) * 25 + gi]);
        red[gg * 24 + gi] = pm;
    }
    __syncthreads();
    if (tid < 24) {
        float m = -INFINITY;
#pragma unroll
        for (int q = 0; q < 8; q++) m = fmaxf(m, red[q * 24 + tid]);
        msh[tid] = m;
    }
    __syncthreads();
    if (tid < 192) {
        const float m = msh[gi];
        float s = 0.f;
        for (int q = 0; q < 36; q++) {
            const int fk = gg * 36 + q;
            const float e = expf(bLsh[fk * 25 + gi] - m);
            bLsh[fk * 25 + gi] = e;
            s += e;
        }
        red[gg * 24 + gi] = s;
    }
    __syncthreads();
    if (tid < 24) {
        float s = 0.f;
#pragma unroll
        for (int q = 0; q < 8; q++) s += red[q * 24 + tid];
        invsh[tid] = 1.f / s;
    }
    __syncthreads();
    for (int idx = tid; idx < FK * 24; idx += 256) {
        const int fk = idx / 24, i = idx % 24;
        bLsh[fk * 25 + i] *= invsh[i];
    }
    __syncthreads();

    // phase 3: out[i][d] = sum_fk Lm[fk][i] * Y[fk][d]
    const int d  = tid & 127;
    const int ih = (tid >> 7) * 12;   // group 0 -> i 0..11, group 1 -> 12..23
    const float* Yp = g_Y + albase + d;
    float acc[12];
#pragma unroll
    for (int ii = 0; ii < 12; ii++) acc[ii] = 0.f;
    for (int fk = 0; fk < FK; fk++) {
        const float yv = Yp[(size_t)fk * HD];
#pragma unroll
        for (int ii = 0; ii < 12; ii++)
            acc[ii] += bLsh[fk * 25 + ih + ii] * yv;
    }
#pragma unroll
    for (int ii = 0; ii < 12; ii++) {
        const int i = ih + ii;
        g_attn[(size_t)(a * 576 + i * 24 + j) * DIM + h * HD + d] = acc[ii];
    }
}

// ---------------- launch --------------------------------------------------
extern "C" void kernel_launch(void* const* d_in, const int* in_sizes, int n_in,
                              void* d_out, int out_size)
{
    (void)in_sizes; (void)n_in; (void)out_size;
    const float* x  = (const float*)d_in[0];
    const float* Wq = (const float*)d_in[1];
    const float* bq = (const float*)d_in[2];
    const float* Wk = (const float*)d_in[3];
    const float* bk = (const float*)d_in[4];
    const float* Wv = (const float*)d_in[5];
    const float* bv = (const float*)d_in[6];
    const float* Wo = (const float*)d_in[7];
    const float* bo = (const float*)d_in[8];
    const float* gq = (const float*)d_in[9];
    const float* gk = (const float*)d_in[10];
    const float* fr = (const float*)d_in[11];
    float* out = (float*)d_out;

    float *qp, *kp, *vp, *ap;
    cudaGetSymbolAddress((void**)&qp, g_q);
    cudaGetSymbolAddress((void**)&kp, g_k);
    cudaGetSymbolAddress((void**)&vp, g_v);
    cudaGetSymbolAddress((void**)&ap, g_attn);

    const dim3 gg(DIM / 128, SEQ / 128);   // (12, 54)
    gemm_bias<<<gg, 256>>>(x, Wq, bq, qp, SEQ, DIM, DIM);
    gemm_bias<<<gg, 256>>>(x, Wk, bk, kp, SEQ, DIM, DIM);
    gemm_bias<<<gg, 256>>>(x, Wv, bv, vp, SEQ, DIM, DIM);

    const float s4 = powf((float)HD, -0.25f);   // sqrt(sm_scale)
    norm_rope<<<SEQ, 256>>>(qp, gq, fr, s4);
    norm_rope<<<SEQ, 256>>>(kp, gk, fr, s4);

    stageA<<<dim3(24, 12, 12), 256>>>();
    stageB<<<dim3(24, 12, 12), 256>>>();

    gemm_bias<<<gg, 256>>>(ap, Wo, bo, out, SEQ, DIM, DIM);
}

// round 2
// speedup vs baseline: 1.0011x; 1.0011x over previous
#include <cuda_runtime.h>
#include <math.h>
#include <stdint.h>

#define SEQ 6912
#define DIM 1536
#define NH  12
#define HD  128
#define Fg  12
#define Hg  24
#define Wg  24
#define FK  288           // f*k = 12*24
#define EPS_NORM 1e-6f
#define CAPF (1.0f/1.000001f)   // min(1/(1+eps), 1e4) with cR == 1

// ---------------- scratch (device globals; no runtime allocation) ----------
__device__ float g_q[SEQ * DIM];
__device__ float g_k[SEQ * DIM];
__device__ float g_v[SEQ * DIM];
__device__ float g_attn[SEQ * DIM];
// layout: [h][a][j][fk][d]  (a in 0..11, j in 0..23, fk = f*24 + k)
__device__ float g_aL[(size_t)NH * Fg * Wg * FK * HD];
__device__ float g_Y [(size_t)NH * Fg * Wg * FK * HD];
__device__ float g_cL[(size_t)NH * Fg * Wg * FK];

// ---------------- GEMM: out[m,o] = sum_k A[m,k] * W[o,k] + bias[o] ----------
// A: [M,K] row-major, W: [O,K] row-major (i.e. computes A @ W^T + b)
// BM=BN=128, BK=8, 256 threads, 8x8 micro-tile.
__global__ __launch_bounds__(256) void gemm_bias(
    const float* __restrict__ A, const float* __restrict__ W,
    const float* __restrict__ bias, float* __restrict__ out,
    int M, int K, int O)
{
    __shared__ float As[8 * 132];
    __shared__ float Ws[8 * 132];

    const int tid = threadIdx.x;
    const int tx = tid & 15;       // 0..15
    const int ty = tid >> 4;       // 0..15
    const int m0 = blockIdx.y * 128;
    const int o0 = blockIdx.x * 128;

    float acc[8][8];
#pragma unroll
    for (int r = 0; r < 8; r++)
#pragma unroll
        for (int c = 0; c < 8; c++) acc[r][c] = 0.f;

    const int lrow = tid >> 1;          // 0..127
    const int lk   = (tid & 1) * 4;     // 0 or 4
    const float* Aptr = A + (size_t)(m0 + lrow) * K + lk;
    const float* Wptr = W + (size_t)(o0 + lrow) * K + lk;

    for (int k0 = 0; k0 < K; k0 += 8) {
        float4 a4 = *reinterpret_cast<const float4*>(Aptr + k0);
        float4 w4 = *reinterpret_cast<const float4*>(Wptr + k0);
        As[(lk + 0) * 132 + lrow] = a4.x;
        As[(lk + 1) * 132 + lrow] = a4.y;
        As[(lk + 2) * 132 + lrow] = a4.z;
        As[(lk + 3) * 132 + lrow] = a4.w;
        Ws[(lk + 0) * 132 + lrow] = w4.x;
        Ws[(lk + 1) * 132 + lrow] = w4.y;
        Ws[(lk + 2) * 132 + lrow] = w4.z;
        Ws[(lk + 3) * 132 + lrow] = w4.w;
        __syncthreads();

#pragma unroll
        for (int kk = 0; kk < 8; kk++) {
            float4 a0 = *reinterpret_cast<const float4*>(&As[kk * 132 + ty * 8]);
            float4 a1 = *reinterpret_cast<const float4*>(&As[kk * 132 + ty * 8 + 4]);
            float4 w0 = *reinterpret_cast<const float4*>(&Ws[kk * 132 + tx * 8]);
            float4 w1 = *reinterpret_cast<const float4*>(&Ws[kk * 132 + tx * 8 + 4]);
            float ar[8] = {a0.x, a0.y, a0.z, a0.w, a1.x, a1.y, a1.z, a1.w};
            float wr[8] = {w0.x, w0.y, w0.z, w0.w, w1.x, w1.y, w1.z, w1.w};
#pragma unroll
            for (int r = 0; r < 8; r++)
#pragma unroll
                for (int c = 0; c < 8; c++)
                    acc[r][c] += ar[r] * wr[c];
        }
        __syncthreads();
    }

#pragma unroll
    for (int r = 0; r < 8; r++) {
        int m = m0 + ty * 8 + r;
#pragma unroll
        for (int c = 0; c < 8; c++) {
            int o = o0 + tx * 8 + c;
            out[(size_t)m * O + o] = acc[r][c] + bias[o];
        }
    }
}

// ---------------- fused RMSNorm (over DIM) + 3D RoPE + scale, in-place ------
__global__ __launch_bounds__(256) void norm_rope(
    float* __restrict__ data, const float* __restrict__ g,
    const float* __restrict__ freqs, float scale)
{
    const int s = blockIdx.x;
    float* row = data + (size_t)s * DIM;
    const int tid = threadIdx.x;

    float ss = 0.f;
    for (int c = tid; c < DIM; c += 256) { float v = row[c]; ss += v * v; }
#pragma unroll
    for (int off = 16; off; off >>= 1) ss += __shfl_xor_sync(~0u, ss, off);
    __shared__ float red[8];
    __shared__ float s_rms;
    if ((tid & 31) == 0) red[tid >> 5] = ss;
    __syncthreads();
    if (tid == 0) {
        float t = 0.f;
#pragma unroll
        for (int i = 0; i < 8; i++) t += red[i];
        s_rms = rsqrtf(t / (float)DIM + EPS_NORM);
    }
    __syncthreads();
    const float rms = s_rms;

    const int fidx = s / (Hg * Wg);
    const int rem  = s % (Hg * Wg);
    const int hidx = rem / Wg;
    const int widx = rem % Wg;

    for (int p = tid; p < DIM / 2; p += 256) {
        const int n = p >> 6;      // head
        const int m = p & 63;      // pair index within head
        const int pos = (m < 22) ? fidx : (m < 43) ? hidx : widx;
        const float ang = freqs[pos * 64 + m];
        float sn, cs;
        sincosf(ang, &sn, &cs);
        const int c0 = n * HD + 2 * m;
        const float xr = row[c0]     * rms * g[c0];
        const float xi = row[c0 + 1] * rms * g[c0 + 1];
        row[c0]     = (xr * cs - xi * sn) * scale;
        row[c0 + 1] = (xr * sn + xi * cs) * scale;
    }
}

// ---------------- Stage A: right softmax over l, produce aL, Y, cL ----------
// grid (k=24, f=12, h=12); 256 threads = 8 warps; each warp processes rows
// r in [0,288) step 8, row -> (a = r/24, j = r%24).
__global__ __launch_bounds__(256) void stageA()
{
    const int kb = blockIdx.x;   // H index shared by queries and keys
    const int f  = blockIdx.y;
    const int h  = blockIdx.z;

    __shared__ float Ksh[HD * 25];   // [d][l], stride 25
    __shared__ float Vsh[HD * 25];
    __shared__ float qsh[8 * HD];

    const int tid = threadIdx.x, lane = tid & 31, w = tid >> 5;
    const int sk_base = f * (Hg * Wg) + kb * Wg;

    for (int idx = tid; idx < 24 * HD; idx += 256) {
        const int l = idx >> 7, d = idx & 127;
        const size_t gidx = (size_t)(sk_base + l) * DIM + h * HD + d;
        Ksh[d * 25 + l] = g_k[gidx];
        Vsh[d * 25 + l] = g_v[gidx];
    }
    __syncthreads();

    for (int r = w; r < Fg * Wg; r += 8) {
        const int a = r / Wg, j = r % Wg;
        const int sq = a * (Hg * Wg) + kb * Wg + j;

        // stage q row into smem
        const float4 q4 = *reinterpret_cast<const float4*>(
            &g_q[(size_t)sq * DIM + h * HD + lane * 4]);
        *reinterpret_cast<float4*>(&qsh[w * HD + lane * 4]) = q4;
        __syncwarp();

        float z;
        if (lane < 24) {
            float acc = 0.f;
#pragma unroll 8
            for (int d = 0; d < HD; d++)
                acc += qsh[w * HD + d] * Ksh[d * 25 + lane];
            z = acc * CAPF;
        } else {
            z = -INFINITY;
        }
        float zm = z;
#pragma unroll
        for (int off = 16; off; off >>= 1)
            zm = fmaxf(zm, __shfl_xor_sync(~0u, zm, off));
        const float e  = (lane < 24) ? expf(z - zm) : 0.f;
        const float et = (lane < 24) ? e * (z - zm) : 0.f;
        float es = e, ets = et;
#pragma unroll
        for (int off = 16; off; off >>= 1) {
            es  += __shfl_xor_sync(~0u, es, off);
            ets += __shfl_xor_sync(~0u, ets, off);
        }
        const float inv = 1.f / es;
        const float R   = e * inv;
        const float cl  = ets * inv - logf(es);

        float accA[4] = {0.f, 0.f, 0.f, 0.f};
        float accY[4] = {0.f, 0.f, 0.f, 0.f};
#pragma unroll
        for (int l = 0; l < 24; l++) {
            const float rl = __shfl_sync(~0u, R, l);
#pragma unroll
            for (int t = 0; t < 4; t++) {
                const int d = lane + 32 * t;
                accA[t] += rl * Ksh[d * 25 + l];
                accY[t] += rl * Vsh[d * 25 + l];
            }
        }

        const size_t rowbase =
            ((size_t)(h * Fg + a) * Wg + j) * FK + (f * 24 + kb);
        const size_t ob = rowbase * HD;
#pragma unroll
        for (int t = 0; t < 4; t++) {
            g_aL[ob + lane + 32 * t] = accA[t];
            g_Y [ob + lane + 32 * t] = accY[t];
        }
        if (lane == 0) g_cL[rowbase] = cl;
        __syncwarp();
    }
}

// ---------------- Stage B: left block softmax over (f,k), output attn -------
// grid (j=24, a=12, h=12); 256 threads.
__global__ __launch_bounds__(256) void stageB()
{
    const int j = blockIdx.x;
    const int a = blockIdx.y;
    const int h = blockIdx.z;

    __shared__ float Qsh[HD * 25];    // [d][i]
    __shared__ float bLsh[FK * 25];   // [fk][i], stride 25
    __shared__ float alsh[8 * HD];
    __shared__ float red[8 * 24];
    __shared__ float msh[24], invsh[24];

    const int tid = threadIdx.x, lane = tid & 31, w = tid >> 5;

    for (int idx = tid; idx < 24 * HD; idx += 256) {
        const int i = idx >> 7, d = idx & 127;
        Qsh[d * 25 + i] =
            g_q[(size_t)(a * 576 + i * 24 + j) * DIM + h * HD + d];
    }
    __syncthreads();

    const size_t base   = (size_t)(h * Fg + a) * Wg + j;
    const size_t albase = base * FK * HD;
    const size_t clbase = base * FK;

    // phase 1: bL[fk][i] = aL[fk,:] . Q[i,:] - cL[fk]
    for (int fk = w; fk < FK; fk += 8) {
        const float4 a4 = *reinterpret_cast<const float4*>(
            &g_aL[albase + (size_t)fk * HD + lane * 4]);
        *reinterpret_cast<float4*>(&alsh[w * HD + lane * 4]) = a4;
        __syncwarp();
        if (lane < 24) {
            float b = 0.f;
#pragma unroll 8
            for (int d = 0; d < HD; d++)
                b += alsh[w * HD + d] * Qsh[d * 25 + lane];
            bLsh[fk * 25 + lane] = b - g_cL[clbase + fk];
        }
        __syncwarp();
    }
    __syncthreads();

    // phase 2: softmax over fk (288) for each i (24)
    const int gi = tid % 24, gg = tid / 24;
    if (tid < 192) {
        float pm = -INFINITY;
        for (int q = 0; q < 36; q++)
            pm = fmaxf(pm, bLsh[(gg * 36 + q) * 25 + gi]);
        red[gg * 24 + gi] = pm;
    }
    __syncthreads();
    if (tid < 24) {
        float m = -INFINITY;
#pragma unroll
        for (int q = 0; q < 8; q++) m = fmaxf(m, red[q * 24 + tid]);
        msh[tid] = m;
    }
    __syncthreads();
    if (tid < 192) {
        const float m = msh[gi];
        float s = 0.f;
        for (int q = 0; q < 36; q++) {
            const int fk = gg * 36 + q;
            const float e = expf(bLsh[fk * 25 + gi] - m);
            bLsh[fk * 25 + gi] = e;
            s += e;
        }
        red[gg * 24 + gi] = s;
    }
    __syncthreads();
    if (tid < 24) {
        float s = 0.f;
#pragma unroll
        for (int q = 0; q < 8; q++) s += red[q * 24 + tid];
        invsh[tid] = 1.f / s;
    }
    __syncthreads();
    for (int idx = tid; idx < FK * 24; idx += 256) {
        const int fk = idx / 24, i = idx % 24;
        bLsh[fk * 25 + i] *= invsh[i];
    }
    __syncthreads();

    // phase 3: out[i][d] = sum_fk Lm[fk][i] * Y[fk][d]
    const int d  = tid & 127;
    const int ih = (tid >> 7) * 12;   // group 0 -> i 0..11, group 1 -> 12..23
    const float* Yp = g_Y + albase + d;
    float acc[12];
#pragma unroll
    for (int ii = 0; ii < 12; ii++) acc[ii] = 0.f;
    for (int fk = 0; fk < FK; fk++) {
        const float yv = Yp[(size_t)fk * HD];
#pragma unroll
        for (int ii = 0; ii < 12; ii++)
            acc[ii] += bLsh[fk * 25 + ih + ii] * yv;
    }
#pragma unroll
    for (int ii = 0; ii < 12; ii++) {
        const int i = ih + ii;
        g_attn[(size_t)(a * 576 + i * 24 + j) * DIM + h * HD + d] = acc[ii];
    }
}

// ---------------- launch --------------------------------------------------
extern "C" void kernel_launch(void* const* d_in, const int* in_sizes, int n_in,
                              void* d_out, int out_size)
{
    (void)in_sizes; (void)n_in; (void)out_size;
    const float* x  = (const float*)d_in[0];
    const float* Wq = (const float*)d_in[1];
    const float* bq = (const float*)d_in[2];
    const float* Wk = (const float*)d_in[3];
    const float* bk = (const float*)d_in[4];
    const float* Wv = (const float*)d_in[5];
    const float* bv = (const float*)d_in[6];
    const float* Wo = (const float*)d_in[7];
    const float* bo = (const float*)d_in[8];
    const float* gq = (const float*)d_in[9];
    const float* gk = (const float*)d_in[10];
    const float* fr = (const float*)d_in[11];
    float* out = (float*)d_out;

    float *qp, *kp, *vp, *ap;
    cudaGetSymbolAddress((void**)&qp, g_q);
    cudaGetSymbolAddress((void**)&kp, g_k);
    cudaGetSymbolAddress((void**)&vp, g_v);
    cudaGetSymbolAddress((void**)&ap, g_attn);

    const dim3 gg(DIM / 128, SEQ / 128);   // (12, 54)
    gemm_bias<<<gg, 256>>>(x, Wq, bq, qp, SEQ, DIM, DIM);
    gemm_bias<<<gg, 256>>>(x, Wk, bk, kp, SEQ, DIM, DIM);
    gemm_bias<<<gg, 256>>>(x, Wv, bv, vp, SEQ, DIM, DIM);

    const float s4 = powf((float)HD, -0.25f);   // sqrt(sm_scale)
    norm_rope<<<SEQ, 256>>>(qp, gq, fr, s4);
    norm_rope<<<SEQ, 256>>>(kp, gk, fr, s4);

    stageA<<<dim3(24, 12, 12), 256>>>();
    stageB<<<dim3(24, 12, 12), 256>>>();

    gemm_bias<<<gg, 256>>>(ap, Wo, bo, out, SEQ, DIM, DIM);
}

// round 5
// speedup vs baseline: 1.7311x; 1.7292x over previous
#include <cuda_runtime.h>
#include <math.h>
#include <stdint.h>

#define SEQ 6912
#define DIM 1536
#define NH  12
#define HD  128
#define Fg  12
#define Hg  24
#define Wg  24
#define FK  288           // f*k = 12*24
#define EPS_NORM 1e-6f
#define CAPF (1.0f/1.000001f)   // min(1/(1+eps), 1e4) with cR == 1

// ---------------- scratch (device globals; no runtime allocation) ----------
__device__ float g_q[SEQ * DIM];
__device__ float g_k[SEQ * DIM];
__device__ float g_v[SEQ * DIM];
__device__ float g_attn[SEQ * DIM];
// layout: [h][a][j][fk][d]  (a in 0..11, j in 0..23, fk = f*24 + k)
__device__ float g_aL[(size_t)NH * Fg * Wg * FK * HD];
__device__ float g_Y [(size_t)NH * Fg * Wg * FK * HD];
__device__ float g_cL[(size_t)NH * Fg * Wg * FK];

// ---------------- helpers ---------------------------------------------------
__device__ __forceinline__ void cp16(void* dst, const void* src) {
    uint32_t d = (uint32_t)__cvta_generic_to_shared(dst);
    asm volatile("cp.async.cg.shared.global [%0], [%1], 16;\n" :: "r"(d), "l"(src));
}
__device__ __forceinline__ uint32_t tf32_rn(float x) {
    uint32_t r;
    asm("cvt.rna.tf32.f32 %0, %1;\n" : "=r"(r) : "f"(x));
    return r;
}

// ---------------- tf32 tensor-core GEMM: out = A @ W^T + bias ---------------
// A: [M,K] row-major, W: [O,K] row-major. BM=BN=128, BK=16, 256 threads.
// 8 warps as 2(M)x4(N); warp tile 64x32 via m16n8k8 tf32 mma.
// Operands rounded to tf32 with RNA (bias-free) before the MMA.
#define LDS_PAD 20
__global__ __launch_bounds__(256) void gemm_tf32(
    const float* __restrict__ A, const float* __restrict__ W,
    const float* __restrict__ bias, float* __restrict__ out,
    int M, int K, int O)
{
    __shared__ float As[2][128 * LDS_PAD];
    __shared__ float Ws[2][128 * LDS_PAD];

    const int tid  = threadIdx.x;
    const int lane = tid & 31;
    const int warp = tid >> 5;
    const int gid  = lane >> 2;       // 0..7
    const int tg   = lane & 3;        // 0..3
    const int wm   = (warp & 1) * 64;
    const int wn   = (warp >> 1) * 32;
    const int m0   = blockIdx.y * 128;
    const int o0   = blockIdx.x * 128;

    const int lrow = tid >> 2;        // 0..63
    const int lcol = (tid & 3) * 4;   // 0,4,8,12

    const float* Agp = A + (size_t)(m0 + lrow) * K + lcol;
    const float* Wgp = W + (size_t)(o0 + lrow) * K + lcol;

    float acc[4][4][4];
#pragma unroll
    for (int mt = 0; mt < 4; mt++)
#pragma unroll
        for (int nt = 0; nt < 4; nt++)
#pragma unroll
            for (int r = 0; r < 4; r++) acc[mt][nt][r] = 0.f;

    const int nIter = K / 16;

    // prologue: stage 0
    cp16(&As[0][lrow * LDS_PAD + lcol], Agp);
    cp16(&As[0][(lrow + 64) * LDS_PAD + lcol], Agp + (size_t)64 * K);
    cp16(&Ws[0][lrow * LDS_PAD + lcol], Wgp);
    cp16(&Ws[0][(lrow + 64) * LDS_PAD + lcol], Wgp + (size_t)64 * K);
    asm volatile("cp.async.commit_group;\n");

    for (int it = 0; it < nIter; ++it) {
        if (it + 1 < nIter) {
            const int nb = (it + 1) & 1;
            const int ko = (it + 1) * 16;
            cp16(&As[nb][lrow * LDS_PAD + lcol], Agp + ko);
            cp16(&As[nb][(lrow + 64) * LDS_PAD + lcol], Agp + (size_t)64 * K + ko);
            cp16(&Ws[nb][lrow * LDS_PAD + lcol], Wgp + ko);
            cp16(&Ws[nb][(lrow + 64) * LDS_PAD + lcol], Wgp + (size_t)64 * K + ko);
        }
        asm volatile("cp.async.commit_group;\n");
        asm volatile("cp.async.wait_group 1;\n");
        __syncthreads();

        const float* as = As[it & 1];
        const float* ws = Ws[it & 1];
#pragma unroll
        for (int kk = 0; kk < 16; kk += 8) {
            uint32_t a[4][4], b[4][2];
#pragma unroll
            for (int mt = 0; mt < 4; mt++) {
                const int mr = wm + mt * 16 + gid;
                a[mt][0] = tf32_rn(as[mr * LDS_PAD + kk + tg]);
                a[mt][1] = tf32_rn(as[(mr + 8) * LDS_PAD + kk + tg]);
                a[mt][2] = tf32_rn(as[mr * LDS_PAD + kk + tg + 4]);
                a[mt][3] = tf32_rn(as[(mr + 8) * LDS_PAD + kk + tg + 4]);
            }
#pragma unroll
            for (int nt = 0; nt < 4; nt++) {
                const int nr = wn + nt * 8 + gid;
                b[nt][0] = tf32_rn(ws[nr * LDS_PAD + kk + tg]);
                b[nt][1] = tf32_rn(ws[nr * LDS_PAD + kk + tg + 4]);
            }
#pragma unroll
            for (int mt = 0; mt < 4; mt++)
#pragma unroll
                for (int nt = 0; nt < 4; nt++)
                    asm volatile(
                        "mma.sync.aligned.m16n8k8.row.col.f32.tf32.tf32.f32 "
                        "{%0,%1,%2,%3}, {%4,%5,%6,%7}, {%8,%9}, {%0,%1,%2,%3};\n"
                        : "+f"(acc[mt][nt][0]), "+f"(acc[mt][nt][1]),
                          "+f"(acc[mt][nt][2]), "+f"(acc[mt][nt][3])
                        : "r"(a[mt][0]), "r"(a[mt][1]), "r"(a[mt][2]), "r"(a[mt][3]),
                          "r"(b[nt][0]), "r"(b[nt][1]));
        }
        __syncthreads();
    }

    // epilogue
#pragma unroll
    for (int mt = 0; mt < 4; mt++) {
        const int m = m0 + wm + mt * 16 + gid;
#pragma unroll
        for (int nt = 0; nt < 4; nt++) {
            const int o = o0 + wn + nt * 8 + tg * 2;
            const float b0 = bias[o], b1 = bias[o + 1];
            float2 v0 = make_float2(acc[mt][nt][0] + b0, acc[mt][nt][1] + b1);
            float2 v1 = make_float2(acc[mt][nt][2] + b0, acc[mt][nt][3] + b1);
            *reinterpret_cast<float2*>(&out[(size_t)m * O + o]) = v0;
            *reinterpret_cast<float2*>(&out[(size_t)(m + 8) * O + o]) = v1;
        }
    }
}

// ---------------- fused RMSNorm (over DIM) + 3D RoPE + scale, in-place ------
__global__ __launch_bounds__(256) void norm_rope(
    float* __restrict__ data, const float* __restrict__ g,
    const float* __restrict__ freqs, float scale)
{
    const int s = blockIdx.x;
    float* row = data + (size_t)s * DIM;
    const int tid = threadIdx.x;

    float ss = 0.f;
    for (int c = tid; c < DIM; c += 256) { float v = row[c]; ss += v * v; }
#pragma unroll
    for (int off = 16; off; off >>= 1) ss += __shfl_xor_sync(~0u, ss, off);
    __shared__ float red[8];
    __shared__ float s_rms;
    if ((tid & 31) == 0) red[tid >> 5] = ss;
    __syncthreads();
    if (tid == 0) {
        float t = 0.f;
#pragma unroll
        for (int i = 0; i < 8; i++) t += red[i];
        s_rms = rsqrtf(t / (float)DIM + EPS_NORM);
    }
    __syncthreads();
    const float rms = s_rms;

    const int fidx = s / (Hg * Wg);
    const int rem  = s % (Hg * Wg);
    const int hidx = rem / Wg;
    const int widx = rem % Wg;

    for (int p = tid; p < DIM / 2; p += 256) {
        const int n = p >> 6;      // head
        const int m = p & 63;      // pair index within head
        const int pos = (m < 22) ? fidx : (m < 43) ? hidx : widx;
        const float ang = freqs[pos * 64 + m];
        float sn, cs;
        sincosf(ang, &sn, &cs);
        const int c0 = n * HD + 2 * m;
        const float xr = row[c0]     * rms * g[c0];
        const float xi = row[c0 + 1] * rms * g[c0 + 1];
        row[c0]     = (xr * cs - xi * sn) * scale;
        row[c0 + 1] = (xr * sn + xi * cs) * scale;
    }
}

// ---------------- Stage A: right softmax over l, produce aL, Y, cL ----------
__global__ __launch_bounds__(256) void stageA()
{
    const int kb = blockIdx.x;   // H index shared by queries and keys
    const int f  = blockIdx.y;
    const int h  = blockIdx.z;

    __shared__ float Ksh[HD * 25];   // [d][l], stride 25
    __shared__ float Vsh[HD * 25];
    __shared__ float qsh[8 * HD];

    const int tid = threadIdx.x, lane = tid & 31, w = tid >> 5;
    const int sk_base = f * (Hg * Wg) + kb * Wg;

    for (int idx = tid; idx < 24 * HD; idx += 256) {
        const int l = idx >> 7, d = idx & 127;
        const size_t gidx = (size_t)(sk_base + l) * DIM + h * HD + d;
        Ksh[d * 25 + l] = g_k[gidx];
        Vsh[d * 25 + l] = g_v[gidx];
    }
    __syncthreads();

    for (int r = w; r < Fg * Wg; r += 8) {
        const int a = r / Wg, j = r % Wg;
        const int sq = a * (Hg * Wg) + kb * Wg + j;

        const float4 q4 = *reinterpret_cast<const float4*>(
            &g_q[(size_t)sq * DIM + h * HD + lane * 4]);
        *reinterpret_cast<float4*>(&qsh[w * HD + lane * 4]) = q4;
        __syncwarp();

        float z;
        if (lane < 24) {
            float acc = 0.f;
#pragma unroll 8
            for (int d = 0; d < HD; d++)
                acc += qsh[w * HD + d] * Ksh[d * 25 + lane];
            z = acc * CAPF;
        } else {
            z = -INFINITY;
        }
        float zm = z;
#pragma unroll
        for (int off = 16; off; off >>= 1)
            zm = fmaxf(zm, __shfl_xor_sync(~0u, zm, off));
        const float e  = (lane < 24) ? expf(z - zm) : 0.f;
        const float et = (lane < 24) ? e * (z - zm) : 0.f;
        float es = e, ets = et;
#pragma unroll
        for (int off = 16; off; off >>= 1) {
            es  += __shfl_xor_sync(~0u, es, off);
            ets += __shfl_xor_sync(~0u, ets, off);
        }
        const float inv = 1.f / es;
        const float R   = e * inv;
        const float cl  = ets * inv - logf(es);

        float accA[4] = {0.f, 0.f, 0.f, 0.f};
        float accY[4] = {0.f, 0.f, 0.f, 0.f};
#pragma unroll
        for (int l = 0; l < 24; l++) {
            const float rl = __shfl_sync(~0u, R, l);
#pragma unroll
            for (int t = 0; t < 4; t++) {
                const int d = lane + 32 * t;
                accA[t] += rl * Ksh[d * 25 + l];
                accY[t] += rl * Vsh[d * 25 + l];
            }
        }

        const size_t rowbase =
            ((size_t)(h * Fg + a) * Wg + j) * FK + (f * 24 + kb);
        const size_t ob = rowbase * HD;
#pragma unroll
        for (int t = 0; t < 4; t++) {
            g_aL[ob + lane + 32 * t] = accA[t];
            g_Y [ob + lane + 32 * t] = accY[t];
        }
        if (lane == 0) g_cL[rowbase] = cl;
        __syncwarp();
    }
}

// ---------------- Stage B: left block softmax over (f,k), output attn -------
__global__ __launch_bounds__(256) void stageB()
{
    const int j = blockIdx.x;
    const int a = blockIdx.y;
    const int h = blockIdx.z;

    __shared__ float Qsh[HD * 25];    // [d][i]
    __shared__ float bLsh[FK * 25];   // [fk][i], stride 25
    __shared__ float alsh[8 * HD];
    __shared__ float red[8 * 24];
    __shared__ float msh[24], invsh[24];

    const int tid = threadIdx.x, lane = tid & 31, w = tid >> 5;

    for (int idx = tid; idx < 24 * HD; idx += 256) {
        const int i = idx >> 7, d = idx & 127;
        Qsh[d * 25 + i] =
            g_q[(size_t)(a * 576 + i * 24 + j) * DIM + h * HD + d];
    }
    __syncthreads();

    const size_t base   = (size_t)(h * Fg + a) * Wg + j;
    const size_t albase = base * FK * HD;
    const size_t clbase = base * FK;

    for (int fk = w; fk < FK; fk += 8) {
        const float4 a4 = *reinterpret_cast<const float4*>(
            &g_aL[albase + (size_t)fk * HD + lane * 4]);
        *reinterpret_cast<float4*>(&alsh[w * HD + lane * 4]) = a4;
        __syncwarp();
        if (lane < 24) {
            float b = 0.f;
#pragma unroll 8
            for (int d = 0; d < HD; d++)
                b += alsh[w * HD + d] * Qsh[d * 25 + lane];
            bLsh[fk * 25 + lane] = b - g_cL[clbase + fk];
        }
        __syncwarp();
    }
    __syncthreads();

    const int gi = tid % 24, gg = tid / 24;
    if (tid < 192) {
        float pm = -INFINITY;
        for (int q = 0; q < 36; q++)
            pm = fmaxf(pm, bLsh[(gg * 36 + q) * 25 + gi]);
        red[gg * 24 + gi] = pm;
    }
    __syncthreads();
    if (tid < 24) {
        float m = -INFINITY;
#pragma unroll
        for (int q = 0; q < 8; q++) m = fmaxf(m, red[q * 24 + tid]);
        msh[tid] = m;
    }
    __syncthreads();
    if (tid < 192) {
        const float m = msh[gi];
        float s = 0.f;
        for (int q = 0; q < 36; q++) {
            const int fk = gg * 36 + q;
            const float e = expf(bLsh[fk * 25 + gi] - m);
            bLsh[fk * 25 + gi] = e;
            s += e;
        }
        red[gg * 24 + gi] = s;
    }
    __syncthreads();
    if (tid < 24) {
        float s = 0.f;
#pragma unroll
        for (int q = 0; q < 8; q++) s += red[q * 24 + tid];
        invsh[tid] = 1.f / s;
    }
    __syncthreads();
    for (int idx = tid; idx < FK * 24; idx += 256) {
        const int fk = idx / 24, i = idx % 24;
        bLsh[fk * 25 + i] *= invsh[i];
    }
    __syncthreads();

    const int d  = tid & 127;
    const int ih = (tid >> 7) * 12;
    const float* Yp = g_Y + albase + d;
    float acc[12];
#pragma unroll
    for (int ii = 0; ii < 12; ii++) acc[ii] = 0.f;
    for (int fk = 0; fk < FK; fk++) {
        const float yv = Yp[(size_t)fk * HD];
#pragma unroll
        for (int ii = 0; ii < 12; ii++)
            acc[ii] += bLsh[fk * 25 + ih + ii] * yv;
    }
#pragma unroll
    for (int ii = 0; ii < 12; ii++) {
        const int i = ih + ii;
        g_attn[(size_t)(a * 576 + i * 24 + j) * DIM + h * HD + d] = acc[ii];
    }
}

// ---------------- launch --------------------------------------------------
extern "C" void kernel_launch(void* const* d_in, const int* in_sizes, int n_in,
                              void* d_out, int out_size)
{
    (void)in_sizes; (void)n_in; (void)out_size;
    const float* x  = (const float*)d_in[0];
    const float* Wq = (const float*)d_in[1];
    const float* bq = (const float*)d_in[2];
    const float* Wk = (const float*)d_in[3];
    const float* bk = (const float*)d_in[4];
    const float* Wv = (const float*)d_in[5];
    const float* bv = (const float*)d_in[6];
    const float* Wo = (const float*)d_in[7];
    const float* bo = (const float*)d_in[8];
    const float* gq = (const float*)d_in[9];
    const float* gk = (const float*)d_in[10];
    const float* fr = (const float*)d_in[11];
    float* out = (float*)d_out;

    float *qp, *kp, *vp, *ap;
    cudaGetSymbolAddress((void**)&qp, g_q);
    cudaGetSymbolAddress((void**)&kp, g_k);
    cudaGetSymbolAddress((void**)&vp, g_v);
    cudaGetSymbolAddress((void**)&ap, g_attn);

    const dim3 gg(DIM / 128, SEQ / 128);   // (12, 54)
    gemm_tf32<<<gg, 256>>>(x, Wq, bq, qp, SEQ, DIM, DIM);
    gemm_tf32<<<gg, 256>>>(x, Wk, bk, kp, SEQ, DIM, DIM);
    gemm_tf32<<<gg, 256>>>(x, Wv, bv, vp, SEQ, DIM, DIM);

    const float s4 = powf((float)HD, -0.25f);   // sqrt(sm_scale)
    norm_rope<<<SEQ, 256>>>(qp, gq, fr, s4);
    norm_rope<<<SEQ, 256>>>(kp, gk, fr, s4);

    stageA<<<dim3(24, 12, 12), 256>>>();
    stageB<<<dim3(24, 12, 12), 256>>>();

    gemm_tf32<<<gg, 256>>>(ap, Wo, bo, out, SEQ, DIM, DIM);
}

// round 6
// speedup vs baseline: 1.7398x; 1.0050x over previous
#include <cuda_runtime.h>
#include <math.h>
#include <stdint.h>

#define SEQ 6912
#define DIM 1536
#define NH  12
#define HD  128
#define Fg  12
#define Hg  24
#define Wg  24
#define FK  288           // f*k = 12*24
#define EPS_NORM 1e-6f
#define CAPF (1.0f/1.000001f)   // min(1/(1+eps), 1e4) with cR == 1

// ---------------- scratch (device globals; no runtime allocation) ----------
__device__ float g_q[SEQ * DIM];
__device__ float g_k[SEQ * DIM];
__device__ float g_v[SEQ * DIM];
__device__ float g_attn[SEQ * DIM];
__device__ float g_xr[SEQ * DIM];          // tf32-rounded, k-permuted activations
__device__ float g_wq[DIM * DIM];          // tf32-rounded, k-permuted weights
__device__ float g_wk[DIM * DIM];
__device__ float g_wv[DIM * DIM];
__device__ float g_wo[DIM * DIM];
// layout: [h][a][j][fk][d]  (a in 0..11, j in 0..23, fk = f*24 + k)
__device__ float g_aL[(size_t)NH * Fg * Wg * FK * HD];
__device__ float g_Y [(size_t)NH * Fg * Wg * FK * HD];
__device__ float g_cL[(size_t)NH * Fg * Wg * FK];

// ---------------- helpers ---------------------------------------------------
__device__ __forceinline__ void cp16(void* dst, const void* src) {
    uint32_t d = (uint32_t)__cvta_generic_to_shared(dst);
    asm volatile("cp.async.cg.shared.global [%0], [%1], 16;\n" :: "r"(d), "l"(src));
}
__device__ __forceinline__ float tf32f(float x) {
    uint32_t r;
    asm("cvt.rna.tf32.f32 %0, %1;\n" : "=r"(r) : "f"(x));
    return __uint_as_float(r);
}

// ---------------- pre-pass: tf32 RNA rounding + k-permutation ---------------
// Within each 8-element k-group, new layout [o0,o4,o1,o5,o2,o6,o3,o7] so that
// mma fragment pairs (tg, tg+4) are adjacent -> LDS.64 in the GEMM mainloop.
__global__ __launch_bounds__(256) void round_permute(
    const float* __restrict__ in, float* __restrict__ out, int n8)
{
    const int i = blockIdx.x * 256 + threadIdx.x;
    if (i >= n8) return;
    const float4* p = reinterpret_cast<const float4*>(in) + (size_t)i * 2;
    const float4 x0 = p[0], x1 = p[1];
    float4 y0 = make_float4(tf32f(x0.x), tf32f(x1.x), tf32f(x0.y), tf32f(x1.y));
    float4 y1 = make_float4(tf32f(x0.z), tf32f(x1.z), tf32f(x0.w), tf32f(x1.w));
    float4* q = reinterpret_cast<float4*>(out) + (size_t)i * 2;
    q[0] = y0; q[1] = y1;
}

// ---------------- tf32 tensor-core GEMM: out = A @ W^T + bias ---------------
// A, W pre-rounded to tf32 and k-permuted. BM=BN=128, BK=16, 256 threads.
// 8 warps as 2(M)x4(N); warp tile 64x32 via m16n8k8 tf32 mma. All fragment
// loads are LDS.64 thanks to the permuted layout; no cvt in the mainloop.
#define PAD 24
__global__ __launch_bounds__(256) void gemm_tf32p(
    const float* __restrict__ A, const float* __restrict__ W,
    const float* __restrict__ bias, float* __restrict__ out,
    int M, int K, int O)
{
    __shared__ float As[2][128 * PAD];
    __shared__ float Ws[2][128 * PAD];

    const int tid  = threadIdx.x;
    const int lane = tid & 31;
    const int warp = tid >> 5;
    const int gid  = lane >> 2;       // 0..7
    const int tg   = lane & 3;        // 0..3
    const int wm   = (warp & 1) * 64;
    const int wn   = (warp >> 1) * 32;
    const int m0   = blockIdx.y * 128;
    const int o0   = blockIdx.x * 128;

    const int lrow = tid >> 2;        // 0..63
    const int lcol = (tid & 3) * 4;   // 0,4,8,12

    const float* Agp = A + (size_t)(m0 + lrow) * K + lcol;
    const float* Wgp = W + (size_t)(o0 + lrow) * K + lcol;

    float acc[4][4][4];
#pragma unroll
    for (int mt = 0; mt < 4; mt++)
#pragma unroll
        for (int nt = 0; nt < 4; nt++)
#pragma unroll
            for (int r = 0; r < 4; r++) acc[mt][nt][r] = 0.f;

    const int nIter = K / 16;

    cp16(&As[0][lrow * PAD + lcol], Agp);
    cp16(&As[0][(lrow + 64) * PAD + lcol], Agp + (size_t)64 * K);
    cp16(&Ws[0][lrow * PAD + lcol], Wgp);
    cp16(&Ws[0][(lrow + 64) * PAD + lcol], Wgp + (size_t)64 * K);
    asm volatile("cp.async.commit_group;\n");

    for (int it = 0; it < nIter; ++it) {
        if (it + 1 < nIter) {
            const int nb = (it + 1) & 1;
            const int ko = (it + 1) * 16;
            cp16(&As[nb][lrow * PAD + lcol], Agp + ko);
            cp16(&As[nb][(lrow + 64) * PAD + lcol], Agp + (size_t)64 * K + ko);
            cp16(&Ws[nb][lrow * PAD + lcol], Wgp + ko);
            cp16(&Ws[nb][(lrow + 64) * PAD + lcol], Wgp + (size_t)64 * K + ko);
        }
        asm volatile("cp.async.commit_group;\n");
        asm volatile("cp.async.wait_group 1;\n");
        __syncthreads();

        const float* as = As[it & 1];
        const float* ws = Ws[it & 1];
#pragma unroll
        for (int kk = 0; kk < 16; kk += 8) {
            uint32_t a[4][4], b[4][2];
#pragma unroll
            for (int mt = 0; mt < 4; mt++) {
                const int mr = wm + mt * 16 + gid;
                const float2 pa = *reinterpret_cast<const float2*>(
                    &as[mr * PAD + kk + 2 * tg]);
                const float2 pb = *reinterpret_cast<const float2*>(
                    &as[(mr + 8) * PAD + kk + 2 * tg]);
                a[mt][0] = __float_as_uint(pa.x);
                a[mt][1] = __float_as_uint(pb.x);
                a[mt][2] = __float_as_uint(pa.y);
                a[mt][3] = __float_as_uint(pb.y);
            }
#pragma unroll
            for (int nt = 0; nt < 4; nt++) {
                const int nr = wn + nt * 8 + gid;
                const float2 pw = *reinterpret_cast<const float2*>(
                    &ws[nr * PAD + kk + 2 * tg]);
                b[nt][0] = __float_as_uint(pw.x);
                b[nt][1] = __float_as_uint(pw.y);
            }
#pragma unroll
            for (int mt = 0; mt < 4; mt++)
#pragma unroll
                for (int nt = 0; nt < 4; nt++)
                    asm volatile(
                        "mma.sync.aligned.m16n8k8.row.col.f32.tf32.tf32.f32 "
                        "{%0,%1,%2,%3}, {%4,%5,%6,%7}, {%8,%9}, {%0,%1,%2,%3};\n"
                        : "+f"(acc[mt][nt][0]), "+f"(acc[mt][nt][1]),
                          "+f"(acc[mt][nt][2]), "+f"(acc[mt][nt][3])
                        : "r"(a[mt][0]), "r"(a[mt][1]), "r"(a[mt][2]), "r"(a[mt][3]),
                          "r"(b[nt][0]), "r"(b[nt][1]));
        }
        __syncthreads();
    }

#pragma unroll
    for (int mt = 0; mt < 4; mt++) {
        const int m = m0 + wm + mt * 16 + gid;
#pragma unroll
        for (int nt = 0; nt < 4; nt++) {
            const int o = o0 + wn + nt * 8 + tg * 2;
            const float b0 = bias[o], b1 = bias[o + 1];
            float2 v0 = make_float2(acc[mt][nt][0] + b0, acc[mt][nt][1] + b1);
            float2 v1 = make_float2(acc[mt][nt][2] + b0, acc[mt][nt][3] + b1);
            *reinterpret_cast<float2*>(&out[(size_t)m * O + o]) = v0;
            *reinterpret_cast<float2*>(&out[(size_t)(m + 8) * O + o]) = v1;
        }
    }
}

// ---------------- fused RMSNorm (over DIM) + 3D RoPE + scale, in-place ------
__global__ __launch_bounds__(256) void norm_rope(
    float* __restrict__ data, const float* __restrict__ g,
    const float* __restrict__ freqs, float scale)
{
    const int s = blockIdx.x;
    float* row = data + (size_t)s * DIM;
    const int tid = threadIdx.x;

    float ss = 0.f;
    for (int c = tid; c < DIM; c += 256) { float v = row[c]; ss += v * v; }
#pragma unroll
    for (int off = 16; off; off >>= 1) ss += __shfl_xor_sync(~0u, ss, off);
    __shared__ float red[8];
    __shared__ float s_rms;
    if ((tid & 31) == 0) red[tid >> 5] = ss;
    __syncthreads();
    if (tid == 0) {
        float t = 0.f;
#pragma unroll
        for (int i = 0; i < 8; i++) t += red[i];
        s_rms = rsqrtf(t / (float)DIM + EPS_NORM);
    }
    __syncthreads();
    const float rms = s_rms;

    const int fidx = s / (Hg * Wg);
    const int rem  = s % (Hg * Wg);
    const int hidx = rem / Wg;
    const int widx = rem % Wg;

    for (int p = tid; p < DIM / 2; p += 256) {
        const int n = p >> 6;
        const int m = p & 63;
        const int pos = (m < 22) ? fidx : (m < 43) ? hidx : widx;
        const float ang = freqs[pos * 64 + m];
        float sn, cs;
        sincosf(ang, &sn, &cs);
        const int c0 = n * HD + 2 * m;
        const float xr = row[c0]     * rms * g[c0];
        const float xi = row[c0 + 1] * rms * g[c0 + 1];
        row[c0]     = (xr * cs - xi * sn) * scale;
        row[c0 + 1] = (xr * sn + xi * cs) * scale;
    }
}

// ---------------- Stage A: right softmax over l, produce aL, Y, cL ----------
__global__ __launch_bounds__(256) void stageA()
{
    const int kb = blockIdx.x;
    const int f  = blockIdx.y;
    const int h  = blockIdx.z;

    __shared__ float Ksh[HD * 25];   // [d][l], stride 25
    __shared__ float Vsh[HD * 25];
    __shared__ float qsh[8 * HD];

    const int tid = threadIdx.x, lane = tid & 31, w = tid >> 5;
    const int sk_base = f * (Hg * Wg) + kb * Wg;

    for (int idx = tid; idx < 24 * HD; idx += 256) {
        const int l = idx >> 7, d = idx & 127;
        const size_t gidx = (size_t)(sk_base + l) * DIM + h * HD + d;
        Ksh[d * 25 + l] = g_k[gidx];
        Vsh[d * 25 + l] = g_v[gidx];
    }
    __syncthreads();

    for (int r = w; r < Fg * Wg; r += 8) {
        const int a = r / Wg, j = r % Wg;
        const int sq = a * (Hg * Wg) + kb * Wg + j;

        const float4 q4 = *reinterpret_cast<const float4*>(
            &g_q[(size_t)sq * DIM + h * HD + lane * 4]);
        *reinterpret_cast<float4*>(&qsh[w * HD + lane * 4]) = q4;
        __syncwarp();

        float z;
        if (lane < 24) {
            float a0 = 0.f, a1 = 0.f, a2 = 0.f, a3 = 0.f;
#pragma unroll 8
            for (int d = 0; d < HD; d += 4) {
                a0 += qsh[w * HD + d]     * Ksh[(d)     * 25 + lane];
                a1 += qsh[w * HD + d + 1] * Ksh[(d + 1) * 25 + lane];
                a2 += qsh[w * HD + d + 2] * Ksh[(d + 2) * 25 + lane];
                a3 += qsh[w * HD + d + 3] * Ksh[(d + 3) * 25 + lane];
            }
            z = ((a0 + a1) + (a2 + a3)) * CAPF;
        } else {
            z = -INFINITY;
        }
        float zm = z;
#pragma unroll
        for (int off = 16; off; off >>= 1)
            zm = fmaxf(zm, __shfl_xor_sync(~0u, zm, off));
        const float e  = (lane < 24) ? expf(z - zm) : 0.f;
        const float et = (lane < 24) ? e * (z - zm) : 0.f;
        float es = e, ets = et;
#pragma unroll
        for (int off = 16; off; off >>= 1) {
            es  += __shfl_xor_sync(~0u, es, off);
            ets += __shfl_xor_sync(~0u, ets, off);
        }
        const float inv = 1.f / es;
        const float R   = e * inv;
        const float cl  = ets * inv - logf(es);

        float accA[4] = {0.f, 0.f, 0.f, 0.f};
        float accY[4] = {0.f, 0.f, 0.f, 0.f};
#pragma unroll
        for (int l = 0; l < 24; l++) {
            const float rl = __shfl_sync(~0u, R, l);
#pragma unroll
            for (int t = 0; t < 4; t++) {
                const int d = lane + 32 * t;
                accA[t] += rl * Ksh[d * 25 + l];
                accY[t] += rl * Vsh[d * 25 + l];
            }
        }

        const size_t rowbase =
            ((size_t)(h * Fg + a) * Wg + j) * FK + (f * 24 + kb);
        const size_t ob = rowbase * HD;
#pragma unroll
        for (int t = 0; t < 4; t++) {
            g_aL[ob + lane + 32 * t] = accA[t];
            g_Y [ob + lane + 32 * t] = accY[t];
        }
        if (lane == 0) g_cL[rowbase] = cl;
        __syncwarp();
    }
}

// ---------------- Stage B: left block softmax over (f,k), output attn -------
__global__ __launch_bounds__(256) void stageB()
{
    const int j = blockIdx.x;
    const int a = blockIdx.y;
    const int h = blockIdx.z;

    __shared__ float Qsh[HD * 25];    // [d][i]
    __shared__ float bLsh[FK * 25];   // [fk][i], stride 25
    __shared__ float alsh[8 * HD];
    __shared__ float red[8 * 24];
    __shared__ float msh[24], invsh[24];

    const int tid = threadIdx.x, lane = tid & 31, w = tid >> 5;

    for (int idx = tid; idx < 24 * HD; idx += 256) {
        const int i = idx >> 7, d = idx & 127;
        Qsh[d * 25 + i] =
            g_q[(size_t)(a * 576 + i * 24 + j) * DIM + h * HD + d];
    }
    __syncthreads();

    const size_t base   = (size_t)(h * Fg + a) * Wg + j;
    const size_t albase = base * FK * HD;
    const size_t clbase = base * FK;

    for (int fk = w; fk < FK; fk += 8) {
        const float4 a4 = *reinterpret_cast<const float4*>(
            &g_aL[albase + (size_t)fk * HD + lane * 4]);
        *reinterpret_cast<float4*>(&alsh[w * HD + lane * 4]) = a4;
        __syncwarp();
        if (lane < 24) {
            float b0 = 0.f, b1 = 0.f, b2 = 0.f, b3 = 0.f;
#pragma unroll 8
            for (int d = 0; d < HD; d += 4) {
                b0 += alsh[w * HD + d]     * Qsh[(d)     * 25 + lane];
                b1 += alsh[w * HD + d + 1] * Qsh[(d + 1) * 25 + lane];
                b2 += alsh[w * HD + d + 2] * Qsh[(d + 2) * 25 + lane];
                b3 += alsh[w * HD + d + 3] * Qsh[(d + 3) * 25 + lane];
            }
            bLsh[fk * 25 + lane] = ((b0 + b1) + (b2 + b3)) - g_cL[clbase + fk];
        }
        __syncwarp();
    }
    __syncthreads();

    const int gi = tid % 24, gg = tid / 24;
    if (tid < 192) {
        float pm = -INFINITY;
        for (int q = 0; q < 36; q++)
            pm = fmaxf(pm, bLsh[(gg * 36 + q) * 25 + gi]);
        red[gg * 24 + gi] = pm;
    }
    __syncthreads();
    if (tid < 24) {
        float m = -INFINITY;
#pragma unroll
        for (int q = 0; q < 8; q++) m = fmaxf(m, red[q * 24 + tid]);
        msh[tid] = m;
    }
    __syncthreads();
    if (tid < 192) {
        const float m = msh[gi];
        float s = 0.f;
        for (int q = 0; q < 36; q++) {
            const int fk = gg * 36 + q;
            const float e = expf(bLsh[fk * 25 + gi] - m);
            bLsh[fk * 25 + gi] = e;
            s += e;
        }
        red[gg * 24 + gi] = s;
    }
    __syncthreads();
    if (tid < 24) {
        float s = 0.f;
#pragma unroll
        for (int q = 0; q < 8; q++) s += red[q * 24 + tid];
        invsh[tid] = 1.f / s;
    }
    __syncthreads();
    for (int idx = tid; idx < FK * 24; idx += 256) {
        const int fk = idx / 24, i = idx % 24;
        bLsh[fk * 25 + i] *= invsh[i];
    }
    __syncthreads();

    const int d  = tid & 127;
    const int ih = (tid >> 7) * 12;
    const float* Yp = g_Y + albase + d;
    float acc[12];
#pragma unroll
    for (int ii = 0; ii < 12; ii++) acc[ii] = 0.f;
    for (int fk = 0; fk < FK; fk++) {
        const float yv = Yp[(size_t)fk * HD];
#pragma unroll
        for (int ii = 0; ii < 12; ii++)
            acc[ii] += bLsh[fk * 25 + ih + ii] * yv;
    }
#pragma unroll
    for (int ii = 0; ii < 12; ii++) {
        const int i = ih + ii;
        g_attn[(size_t)(a * 576 + i * 24 + j) * DIM + h * HD + d] = acc[ii];
    }
}

// ---------------- launch --------------------------------------------------
extern "C" void kernel_launch(void* const* d_in, const int* in_sizes, int n_in,
                              void* d_out, int out_size)
{
    (void)in_sizes; (void)n_in; (void)out_size;
    const float* x  = (const float*)d_in[0];
    const float* Wq = (const float*)d_in[1];
    const float* bq = (const float*)d_in[2];
    const float* Wk = (const float*)d_in[3];
    const float* bk = (const float*)d_in[4];
    const float* Wv = (const float*)d_in[5];
    const float* bv = (const float*)d_in[6];
    const float* Wo = (const float*)d_in[7];
    const float* bo = (const float*)d_in[8];
    const float* gq = (const float*)d_in[9];
    const float* gk = (const float*)d_in[10];
    const float* fr = (const float*)d_in[11];
    float* out = (float*)d_out;

    float *qp, *kp, *vp, *ap, *xr, *wq, *wk, *wv, *wo;
    cudaGetSymbolAddress((void**)&qp, g_q);
    cudaGetSymbolAddress((void**)&kp, g_k);
    cudaGetSymbolAddress((void**)&vp, g_v);
    cudaGetSymbolAddress((void**)&ap, g_attn);
    cudaGetSymbolAddress((void**)&xr, g_xr);
    cudaGetSymbolAddress((void**)&wq, g_wq);
    cudaGetSymbolAddress((void**)&wk, g_wk);
    cudaGetSymbolAddress((void**)&wv, g_wv);
    cudaGetSymbolAddress((void**)&wo, g_wo);

    const int nx8 = SEQ * DIM / 8;       // 1,327,104
    const int nw8 = DIM * DIM / 8;       // 294,912
    round_permute<<<(nx8 + 255) / 256, 256>>>(x, xr, nx8);
    round_permute<<<(nw8 + 255) / 256, 256>>>(Wq, wq, nw8);
    round_permute<<<(nw8 + 255) / 256, 256>>>(Wk, wk, nw8);
    round_permute<<<(nw8 + 255) / 256, 256>>>(Wv, wv, nw8);
    round_permute<<<(nw8 + 255) / 256, 256>>>(Wo, wo, nw8);

    const dim3 gg(DIM / 128, SEQ / 128);   // (12, 54)
    gemm_tf32p<<<gg, 256>>>(xr, wq, bq, qp, SEQ, DIM, DIM);
    gemm_tf32p<<<gg, 256>>>(xr, wk, bk, kp, SEQ, DIM, DIM);
    gemm_tf32p<<<gg, 256>>>(xr, wv, bv, vp, SEQ, DIM, DIM);

    const float s4 = powf((float)HD, -0.25f);   // sqrt(sm_scale)
    norm_rope<<<SEQ, 256>>>(qp, gq, fr, s4);
    norm_rope<<<SEQ, 256>>>(kp, gk, fr, s4);

    stageA<<<dim3(24, 12, 12), 256>>>();
    stageB<<<dim3(24, 12, 12), 256>>>();

    // round+permute attention output, then final projection
    round_permute<<<(nx8 + 255) / 256, 256>>>(ap, xr, nx8);
    gemm_tf32p<<<gg, 256>>>(xr, wo, bo, out, SEQ, DIM, DIM);
}